// round 1
// baseline (speedup 1.0000x reference)
#include <cuda_runtime.h>
#include <cstdint>

#define DIN 128
#define DOUT 128
#define NEG_SLOPE 0.2f
#define MAX_N 50048
#define MAX_EN 860000   // E + N with slack

// ---------------- scratch (no allocations allowed) ----------------
__device__ float    g_xw[(size_t)MAX_N * DOUT];   // x @ W
__device__ float    g_asrc[MAX_N];
__device__ float    g_adst[MAX_N];
__device__ float    g_ev[MAX_EN];                 // per-edge logit, then exp
__device__ unsigned g_maxenc[MAX_N];              // encoded segment max
__device__ float    g_denom[MAX_N];
__device__ int      g_src[MAX_EN];
__device__ int      g_dst[MAX_EN];
__device__ int      g_is64;

// ---------------- helpers ----------------
__device__ __forceinline__ unsigned enc_float(float f) {
    unsigned b = __float_as_uint(f);
    return (b & 0x80000000u) ? ~b : (b | 0x80000000u);   // order-preserving; enc > 0 for all finite f
}
__device__ __forceinline__ float dec_float(unsigned e) {
    return (e & 0x80000000u) ? __uint_as_float(e ^ 0x80000000u) : __uint_as_float(~e);
}

// ---------------- kernels ----------------

// Detect int64 vs int32 edge_index. Reads only 64 bytes (safe for either width).
__global__ void k_detect(const long long* ei, int n) {
    bool ok = true;
#pragma unroll
    for (int i = 0; i < 8; i++) {
        long long v = ei[i];
        if (v < 0 || v >= (long long)n) ok = false;
    }
    g_is64 = ok ? 1 : 0;
}

// Zero out accumulators + output.
__global__ void k_zero(float* out, int n, int tot) {
    int i = blockIdx.x * blockDim.x + threadIdx.x;
    if (i < tot) out[i] = 0.0f;
    if (i < n) { g_denom[i] = 0.0f; g_maxenc[i] = 0u; }
}

// Decode edges (+ append self loops) into int32 scratch.
__global__ void k_decode(const void* ei, int E, int n) {
    int i = blockIdx.x * blockDim.x + threadIdx.x;
    int EN = E + n;
    if (i >= EN) return;
    if (i >= E) { g_src[i] = i - E; g_dst[i] = i - E; return; }
    if (g_is64) {
        const long long* p = (const long long*)ei;
        g_src[i] = (int)p[i];
        g_dst[i] = (int)p[i + E];
    } else {
        const int* p = (const int*)ei;
        g_src[i] = p[i];
        g_dst[i] = p[i + E];
    }
}

// xw = x @ W.  Block: 64 rows x 128 cols, 256 threads, BK=32.
// Thread (ty=tid/32, tx=tid%32) computes rows ty*8..ty*8+7, cols tx*4..tx*4+3.
__global__ __launch_bounds__(256) void k_gemm(const float* __restrict__ x,
                                              const float* __restrict__ W, int n) {
    __shared__ float As[64][32];
    __shared__ float Bs[32][128];
    const int tid = threadIdx.x;
    const int block_row = blockIdx.x * 64;
    const int ty = tid >> 5, tx = tid & 31;
    float acc[8][4] = {};

    for (int k0 = 0; k0 < DIN; k0 += 32) {
        // load A tile: 64x32 floats = 512 float4, 2 per thread
#pragma unroll
        for (int t = tid; t < 512; t += 256) {
            int r = t >> 3, kq = t & 7;
            int row = block_row + r; if (row >= n) row = n - 1;
            *(float4*)&As[r][kq * 4] =
                *(const float4*)(x + (size_t)row * DIN + k0 + kq * 4);
        }
        // load B tile: 32x128 floats = 1024 float4, 4 per thread
#pragma unroll
        for (int t = tid; t < 1024; t += 256) {
            int k = t >> 5, cq = t & 31;
            *(float4*)&Bs[k][cq * 4] =
                *(const float4*)(W + (size_t)(k0 + k) * DOUT + cq * 4);
        }
        __syncthreads();
#pragma unroll
        for (int k = 0; k < 32; k++) {
            float4 b = *(float4*)&Bs[k][tx * 4];
#pragma unroll
            for (int r = 0; r < 8; r++) {
                float a = As[ty * 8 + r][k];
                acc[r][0] += a * b.x;
                acc[r][1] += a * b.y;
                acc[r][2] += a * b.z;
                acc[r][3] += a * b.w;
            }
        }
        __syncthreads();
    }
#pragma unroll
    for (int r = 0; r < 8; r++) {
        int row = block_row + ty * 8 + r;
        if (row < n) {
            float4 v = make_float4(acc[r][0], acc[r][1], acc[r][2], acc[r][3]);
            *(float4*)(g_xw + (size_t)row * DOUT + tx * 4) = v;
        }
    }
}

// Per-node attention logits: a_src[i] = dot(xw[i], att_src), same for dst. One warp per row.
__global__ void k_rowdot(const float* __restrict__ att_src,
                         const float* __restrict__ att_dst, int n) {
    int gtid = blockIdx.x * blockDim.x + threadIdx.x;
    int w = gtid >> 5, lane = gtid & 31;
    if (w >= n) return;
    float4 v = ((const float4*)(g_xw + (size_t)w * DOUT))[lane];
    float4 s = ((const float4*)att_src)[lane];
    float4 d = ((const float4*)att_dst)[lane];
    float ps = v.x * s.x + v.y * s.y + v.z * s.z + v.w * s.w;
    float pd = v.x * d.x + v.y * d.y + v.z * d.z + v.w * d.w;
#pragma unroll
    for (int o = 16; o; o >>= 1) {
        ps += __shfl_xor_sync(0xffffffffu, ps, o);
        pd += __shfl_xor_sync(0xffffffffu, pd, o);
    }
    if (lane == 0) { g_asrc[w] = ps; g_adst[w] = pd; }
}

// Edge logits + segment max (encoded-uint atomicMax).
__global__ void k_elogit(int EN) {
    int i = blockIdx.x * blockDim.x + threadIdx.x;
    if (i >= EN) return;
    int s = g_src[i], d = g_dst[i];
    float e = g_asrc[s] + g_adst[d];
    e = (e > 0.0f) ? e : NEG_SLOPE * e;
    g_ev[i] = e;
    atomicMax(&g_maxenc[d], enc_float(e));
}

// exp(e - max) + segment sum.
__global__ void k_eexp(int EN) {
    int i = blockIdx.x * blockDim.x + threadIdx.x;
    if (i >= EN) return;
    int d = g_dst[i];
    float m = dec_float(g_maxenc[d]);
    float ex = __expf(g_ev[i] - m);
    g_ev[i] = ex;
    atomicAdd(&g_denom[d], ex);
}

// Weighted scatter-aggregate: out[dst] += alpha * xw[src]. One warp per edge,
// float4 per lane, vectorized L2-side reduction.
__global__ void k_agg(float* __restrict__ out, int EN) {
    int gtid = blockIdx.x * blockDim.x + threadIdx.x;
    int w = gtid >> 5, lane = gtid & 31;
    if (w >= EN) return;
    int s = g_src[w], d = g_dst[w];
    float alpha = g_ev[w] / g_denom[d];
    float4 v = ((const float4*)(g_xw + (size_t)s * DOUT))[lane];
    v.x *= alpha; v.y *= alpha; v.z *= alpha; v.w *= alpha;
    float4* o = ((float4*)(out + (size_t)d * DOUT)) + lane;
    asm volatile("red.global.add.v4.f32 [%0], {%1, %2, %3, %4};"
                 :: "l"(o), "f"(v.x), "f"(v.y), "f"(v.z), "f"(v.w)
                 : "memory");
}

// bias + ELU epilogue (in place).
__global__ void k_epi(float* out, const float* __restrict__ bias, int tot) {
    int i = blockIdx.x * blockDim.x + threadIdx.x;
    if (i >= tot) return;
    float v = out[i] + bias[i & (DOUT - 1)];
    out[i] = (v > 0.0f) ? v : expm1f(v);
}

// ---------------- launch ----------------
extern "C" void kernel_launch(void* const* d_in, const int* in_sizes, int n_in,
                              void* d_out, int out_size) {
    const float* x       = (const float*)d_in[0];
    const void*  ei      = d_in[1];
    const float* W       = (const float*)d_in[2];
    const float* att_src = (const float*)d_in[3];
    const float* att_dst = (const float*)d_in[4];
    const float* bias    = (const float*)d_in[5];
    float* out = (float*)d_out;

    const int n  = in_sizes[0] / DIN;
    const int E  = in_sizes[1] / 2;
    const int EN = E + n;
    const int tot = n * DOUT;

    k_detect<<<1, 1>>>((const long long*)ei, n);
    k_zero<<<(tot + 255) / 256, 256>>>(out, n, tot);
    k_decode<<<(EN + 255) / 256, 256>>>(ei, E, n);
    k_gemm<<<(n + 63) / 64, 256>>>(x, W, n);
    k_rowdot<<<(n * 32 + 255) / 256, 256>>>(att_src, att_dst, n);
    k_elogit<<<(EN + 255) / 256, 256>>>(EN);
    k_eexp<<<(EN + 255) / 256, 256>>>(EN);
    k_agg<<<(EN * 32 + 255) / 256, 256>>>(out, EN);
    k_epi<<<(tot + 255) / 256, 256>>>(out, bias, tot);
}

// round 2
// speedup vs baseline: 1.2397x; 1.2397x over previous
#include <cuda_runtime.h>
#include <cstdint>

#define DIN 128
#define DOUT 128
#define NEG_SLOPE 0.2f
#define MAX_N 50048
#define MAX_EN 860000   // E + N with slack

// ---------------- scratch (no allocations allowed) ----------------
__device__ float g_xw[(size_t)MAX_N * DOUT];   // x @ W
__device__ float g_asrc[MAX_N];
__device__ float g_adst[MAX_N];
__device__ int   g_deg[MAX_N];                 // in-degree histogram
__device__ int   g_start[MAX_N + 1];           // CSR row offsets (by dst)
__device__ int   g_cursor[MAX_N];              // scatter cursors
__device__ int   g_csr_src[MAX_EN];            // src node per CSR slot
__device__ float g_ev[MAX_EN];                 // leaky-relu logit per CSR slot
__device__ int   g_is64;

// ---------------- kernels ----------------

// Detect int64 vs int32 edge_index (reads 64 bytes, safe either way).
__global__ void k_detect(const long long* ei, int n) {
    bool ok = true;
#pragma unroll
    for (int i = 0; i < 8; i++) {
        long long v = ei[i];
        if (v < 0 || v >= (long long)n) ok = false;
    }
    g_is64 = ok ? 1 : 0;
}

__global__ void k_zero_deg(int n) {
    int i = blockIdx.x * blockDim.x + threadIdx.x;
    if (i < n) g_deg[i] = 0;
}

// Histogram of destinations (incl. self loops appended at the end).
__global__ void k_hist(const void* ei, int E, int n) {
    int i = blockIdx.x * blockDim.x + threadIdx.x;
    if (i >= E + n) return;
    int d;
    if (i >= E) d = i - E;
    else if (g_is64) d = (int)((const long long*)ei)[i + E];
    else             d = ((const int*)ei)[i + E];
    atomicAdd(&g_deg[d], 1);
}

// xw = x @ W with fused per-row attention dots.
// 128x128 tile, BK=16, 256 threads, 8x8 per-thread register tile.
__global__ __launch_bounds__(256) void k_gemm(const float* __restrict__ x,
                                              const float* __restrict__ W,
                                              const float* __restrict__ att_src,
                                              const float* __restrict__ att_dst,
                                              int n) {
    __shared__ float As[128][17];
    __shared__ float Bs[16][128];
    const int tid = threadIdx.x;
    const int tx = tid & 15, ty = tid >> 4;
    const int row0 = blockIdx.x * 128;
    float acc[8][8] = {};

    for (int k0 = 0; k0 < DIN; k0 += 16) {
        // A tile: 128x16, 2 float4 per thread
        {
            int r = tid >> 2;
            int kq = (tid & 3) * 4;
#pragma unroll
            for (int h = 0; h < 2; h++) {
                int rr = r + h * 64;
                int row = row0 + rr; if (row >= n) row = n - 1;
                float4 v = *(const float4*)(x + (size_t)row * DIN + k0 + kq);
                As[rr][kq + 0] = v.x; As[rr][kq + 1] = v.y;
                As[rr][kq + 2] = v.z; As[rr][kq + 3] = v.w;
            }
        }
        // B tile: 16x128, 2 float4 per thread
        {
            int kb = tid >> 5;
            int cb = (tid & 31) * 4;
#pragma unroll
            for (int h = 0; h < 2; h++)
                *(float4*)&Bs[kb + h * 8][cb] =
                    *(const float4*)(W + (size_t)(k0 + kb + h * 8) * DOUT + cb);
        }
        __syncthreads();
#pragma unroll
        for (int k = 0; k < 16; k++) {
            float a[8], b[8];
#pragma unroll
            for (int r = 0; r < 8; r++) a[r] = As[ty * 8 + r][k];
            float4 b0 = *(float4*)&Bs[k][tx * 8];
            float4 b1 = *(float4*)&Bs[k][tx * 8 + 4];
            b[0] = b0.x; b[1] = b0.y; b[2] = b0.z; b[3] = b0.w;
            b[4] = b1.x; b[5] = b1.y; b[6] = b1.z; b[7] = b1.w;
#pragma unroll
            for (int r = 0; r < 8; r++)
#pragma unroll
                for (int c = 0; c < 8; c++) acc[r][c] += a[r] * b[c];
        }
        __syncthreads();
    }

    // attention vectors for this thread's 8 columns
    float4 s0 = ((const float4*)att_src)[tx * 2];
    float4 s1 = ((const float4*)att_src)[tx * 2 + 1];
    float4 d0 = ((const float4*)att_dst)[tx * 2];
    float4 d1 = ((const float4*)att_dst)[tx * 2 + 1];
    float sv[8] = {s0.x, s0.y, s0.z, s0.w, s1.x, s1.y, s1.z, s1.w};
    float dv[8] = {d0.x, d0.y, d0.z, d0.w, d1.x, d1.y, d1.z, d1.w};

#pragma unroll
    for (int r = 0; r < 8; r++) {
        int row = row0 + ty * 8 + r;
        float ps = 0.f, pd = 0.f;
#pragma unroll
        for (int c = 0; c < 8; c++) { ps += acc[r][c] * sv[c]; pd += acc[r][c] * dv[c]; }
        // reduce across the 16 tx-threads (one 16-lane shfl group)
#pragma unroll
        for (int off = 8; off; off >>= 1) {
            ps += __shfl_down_sync(0xffffffffu, ps, off, 16);
            pd += __shfl_down_sync(0xffffffffu, pd, off, 16);
        }
        if (row < n) {
            float4 v0 = make_float4(acc[r][0], acc[r][1], acc[r][2], acc[r][3]);
            float4 v1 = make_float4(acc[r][4], acc[r][5], acc[r][6], acc[r][7]);
            *(float4*)(g_xw + (size_t)row * DOUT + tx * 8) = v0;
            *(float4*)(g_xw + (size_t)row * DOUT + tx * 8 + 4) = v1;
            if (tx == 0) { g_asrc[row] = ps; g_adst[row] = pd; }
        }
    }
}

// Single-block exclusive scan of g_deg -> g_start/g_cursor (4 elems/thread).
__global__ __launch_bounds__(1024) void k_scan(int n) {
    __shared__ int warp_tot[32];
    __shared__ int s_carry;
    int tid = threadIdx.x, lane = tid & 31, wid = tid >> 5;
    if (tid == 0) s_carry = 0;
    __syncthreads();
    for (int base = 0; base < n; base += 4096) {
        int i0 = base + tid * 4;
        int4 v = make_int4(0, 0, 0, 0);
        if (i0 + 3 < n) v = *(const int4*)&g_deg[i0];
        else {
            if (i0 + 0 < n) v.x = g_deg[i0 + 0];
            if (i0 + 1 < n) v.y = g_deg[i0 + 1];
            if (i0 + 2 < n) v.z = g_deg[i0 + 2];
            if (i0 + 3 < n) v.w = g_deg[i0 + 3];
        }
        int s = v.x + v.y + v.z + v.w;
        int sc = s;
#pragma unroll
        for (int off = 1; off < 32; off <<= 1) {
            int t = __shfl_up_sync(0xffffffffu, sc, off);
            if (lane >= off) sc += t;
        }
        if (lane == 31) warp_tot[wid] = sc;
        __syncthreads();
        if (wid == 0) {
            int wv = warp_tot[lane];
            int wsc = wv;
#pragma unroll
            for (int off = 1; off < 32; off <<= 1) {
                int t = __shfl_up_sync(0xffffffffu, wsc, off);
                if (lane >= off) wsc += t;
            }
            warp_tot[lane] = wsc - wv;   // exclusive
        }
        __syncthreads();
        int excl = s_carry + warp_tot[wid] + (sc - s);
        int a0 = excl, a1 = a0 + v.x, a2 = a1 + v.y, a3 = a2 + v.z;
        if (i0 + 0 < n) { g_start[i0 + 0] = a0; g_cursor[i0 + 0] = a0; }
        if (i0 + 1 < n) { g_start[i0 + 1] = a1; g_cursor[i0 + 1] = a1; }
        if (i0 + 2 < n) { g_start[i0 + 2] = a2; g_cursor[i0 + 2] = a2; }
        if (i0 + 3 < n) { g_start[i0 + 3] = a3; g_cursor[i0 + 3] = a3; }
        __syncthreads();
        if (tid == 1023) s_carry = excl + s;
        __syncthreads();
    }
    if (tid == 0) g_start[n] = s_carry;
}

// Scatter edges into CSR order + fused leaky-relu logit.
__global__ void k_scatter(const void* ei, int E, int n) {
    int i = blockIdx.x * blockDim.x + threadIdx.x;
    if (i >= E + n) return;
    int s, d;
    if (i >= E) { s = d = i - E; }
    else if (g_is64) {
        const long long* p = (const long long*)ei;
        s = (int)p[i]; d = (int)p[i + E];
    } else {
        const int* p = (const int*)ei;
        s = p[i]; d = p[i + E];
    }
    float e = g_asrc[s] + g_adst[d];
    e = (e > 0.0f) ? e : NEG_SLOPE * e;
    int pos = atomicAdd(&g_cursor[d], 1);
    g_csr_src[pos] = s;
    g_ev[pos] = e;
}

// Fused GAT gather: segment softmax + weighted aggregate + bias + ELU.
// One warp per destination node, float4 per lane (128 cols).
__global__ __launch_bounds__(256) void k_gat(float* __restrict__ out,
                                             const float* __restrict__ bias,
                                             int n) {
    int gtid = blockIdx.x * blockDim.x + threadIdx.x;
    int w = gtid >> 5, lane = gtid & 31;
    if (w >= n) return;
    int s0 = g_start[w], s1 = g_start[w + 1];

    // segment max
    float m = -1e30f;
    for (int j = s0 + lane; j < s1; j += 32) m = fmaxf(m, g_ev[j]);
#pragma unroll
    for (int off = 16; off; off >>= 1)
        m = fmaxf(m, __shfl_xor_sync(0xffffffffu, m, off));

    // softmax + weighted aggregate (software-pipelined src/ev prefetch)
    float4 acc = make_float4(0.f, 0.f, 0.f, 0.f);
    float denom = 0.f;
    float ev_n = 0.f; int src_n = 0;
    if (s0 < s1) { ev_n = g_ev[s0]; src_n = g_csr_src[s0]; }
    for (int j = s0; j < s1; j++) {
        float ev_c = ev_n; int src_c = src_n;
        if (j + 1 < s1) { ev_n = g_ev[j + 1]; src_n = g_csr_src[j + 1]; }
        float4 v = ((const float4*)(g_xw + (size_t)src_c * DOUT))[lane];
        float alpha = __expf(ev_c - m);
        denom += alpha;
        acc.x += alpha * v.x; acc.y += alpha * v.y;
        acc.z += alpha * v.z; acc.w += alpha * v.w;
    }

    float r = 1.0f / denom;
    float4 b = ((const float4*)bias)[lane];
    float4 o;
    o.x = acc.x * r + b.x; o.y = acc.y * r + b.y;
    o.z = acc.z * r + b.z; o.w = acc.w * r + b.w;
    o.x = (o.x > 0.f) ? o.x : expm1f(o.x);
    o.y = (o.y > 0.f) ? o.y : expm1f(o.y);
    o.z = (o.z > 0.f) ? o.z : expm1f(o.z);
    o.w = (o.w > 0.f) ? o.w : expm1f(o.w);
    ((float4*)(out + (size_t)w * DOUT))[lane] = o;
}

// ---------------- launch ----------------
extern "C" void kernel_launch(void* const* d_in, const int* in_sizes, int n_in,
                              void* d_out, int out_size) {
    const float* x       = (const float*)d_in[0];
    const void*  ei      = d_in[1];
    const float* W       = (const float*)d_in[2];
    const float* att_src = (const float*)d_in[3];
    const float* att_dst = (const float*)d_in[4];
    const float* bias    = (const float*)d_in[5];
    float* out = (float*)d_out;

    const int n  = in_sizes[0] / DIN;
    const int E  = in_sizes[1] / 2;
    const int EN = E + n;

    k_detect<<<1, 1>>>((const long long*)ei, n);
    k_zero_deg<<<(n + 255) / 256, 256>>>(n);
    k_hist<<<(EN + 255) / 256, 256>>>(ei, E, n);
    k_gemm<<<(n + 127) / 128, 256>>>(x, W, att_src, att_dst, n);
    k_scan<<<1, 1024>>>(n);
    k_scatter<<<(EN + 255) / 256, 256>>>(ei, E, n);
    k_gat<<<(n * 32 + 255) / 256, 256>>>(out, bias, n);
}